// round 12
// baseline (speedup 1.0000x reference)
#include <cuda_runtime.h>

// ---------------------------------------------------------------------------
// GCNEncoder, CSR aggregation + split-TF32 (3xTF32) tensor-core GEMMs.
// W pre-converted once to packed tf32 hi/lo fragments (global); A converted
// once per tile into packed {hi,lo} smem; B double-buffered smem with register
// prefetch, ONE barrier per k-chunk. Mainloop has NO ALU in the mma chain.
//   dinv[i] = rsqrt(indeg[i] + 1)
//   layer(X,W,b): H = X@W
//     out[i] = dinv[i]^2*H[i] + sum_{e: dst=i} dinv[src]*dinv[i]*H[src] + b
//   out = layer2( relu(layer1(x)) )
// edge_index int32. Scratch = __device__ globals. Launch-only host code.
// ---------------------------------------------------------------------------

#define MAXN 50048
#define MAXE 800000
#define FIN  128
#define HID  128
#define FOUT 64

__device__ float g_h1 [MAXN * HID];
__device__ float g_agg[MAXN * HID];
__device__ float g_h2 [MAXN * FOUT];
__device__ float g_dinv[MAXN];
__device__ int   g_deg [MAXN];
__device__ int   g_fill[MAXN];
__device__ int   g_rs  [MAXN + 1];
__device__ int   g_bsum[256];
__device__ int   g_boff[256];
__device__ int2  g_cpak[MAXE];          // {src, float_bits(norm)}
// Packed tf32 W fragments: WP[(t*4+r)*NC + n] = {hi(W[8t+r][n]), hi(W[8t+r+4][n]), lo, lo}
__device__ uint4 g_wp[8192 + 4096];     // W1: 16*4*128, W2: 16*4*64

// ---------------------------------------------------------------------------
__device__ __forceinline__ unsigned f2tf32(float f) {
    unsigned r;
    asm("cvt.rna.tf32.f32 %0, %1;" : "=r"(r) : "f"(f));
    return r;
}

__device__ __forceinline__ void mma_tf32(float (&d)[4], const unsigned (&a)[4],
                                         unsigned b0, unsigned b1) {
    asm volatile(
        "mma.sync.aligned.m16n8k8.row.col.f32.tf32.tf32.f32 "
        "{%0,%1,%2,%3}, {%4,%5,%6,%7}, {%8,%9}, {%0,%1,%2,%3};\n"
        : "+f"(d[0]), "+f"(d[1]), "+f"(d[2]), "+f"(d[3])
        : "r"(a[0]), "r"(a[1]), "r"(a[2]), "r"(a[3]), "r"(b0), "r"(b1));
}

__device__ __forceinline__ uint2 pack_hilo(float v) {
    unsigned h = f2tf32(v);
    unsigned l = f2tf32(v - __uint_as_float(h));
    return make_uint2(h, l);
}

// ---------------------------------------------------------------------------
__global__ void deg_init_k(int n) {
    int i = blockIdx.x * blockDim.x + threadIdx.x;
    if (i < n) { g_deg[i] = 0; g_fill[i] = 0; }
}

__global__ void deg_count_k(const int* __restrict__ dst, int E) {
    int i = blockIdx.x * blockDim.x + threadIdx.x;
    if (i < E) atomicAdd(&g_deg[dst[i]], 1);
}

// Pre-convert W1/W2 into packed tf32 hi/lo fragments.
__global__ void wcvt_k(const float* __restrict__ W1, const float* __restrict__ W2) {
    int i = blockIdx.x * blockDim.x + threadIdx.x;
    float w0, w1;
    if (i < 8192) {                       // W1: t(16) x r(4) x n(128)
        int t = i >> 9, rem = i & 511, r = rem >> 7, nn = rem & 127;
        w0 = W1[(8 * t + r) * 128 + nn];
        w1 = W1[(8 * t + r + 4) * 128 + nn];
    } else if (i < 8192 + 4096) {         // W2: t(16) x r(4) x n(64)
        int j = i - 8192;
        int t = j >> 8, rem = j & 255, r = rem >> 6, nn = rem & 63;
        w0 = W2[(8 * t + r) * 64 + nn];
        w1 = W2[(8 * t + r + 4) * 64 + nn];
    } else return;
    unsigned h0 = f2tf32(w0), h1 = f2tf32(w1);
    unsigned l0 = f2tf32(w0 - __uint_as_float(h0));
    unsigned l1 = f2tf32(w1 - __uint_as_float(h1));
    g_wp[i] = make_uint4(h0, h1, l0, l1);
}

// exclusive scan of g_deg -> g_rs, fused dinv
__global__ void scan1_k(int n) {
    __shared__ int s[256];
    int b = blockIdx.x, t = threadIdx.x;
    int i = b * 256 + t;
    int v = (i < n) ? g_deg[i] : 0;
    if (i < n) g_dinv[i] = rsqrtf((float)(v + 1));
    s[t] = v;
    __syncthreads();
#pragma unroll
    for (int off = 1; off < 256; off <<= 1) {
        int add = (t >= off) ? s[t - off] : 0;
        __syncthreads();
        s[t] += add;
        __syncthreads();
    }
    if (i <= n) g_rs[i] = s[t] - v;
    if (t == 255) g_bsum[b] = s[255];
}

__global__ void scan2_k(int nb) {
    __shared__ int s[256];
    int t = threadIdx.x;
    int v = (t < nb) ? g_bsum[t] : 0;
    s[t] = v;
    __syncthreads();
#pragma unroll
    for (int off = 1; off < 256; off <<= 1) {
        int add = (t >= off) ? s[t - off] : 0;
        __syncthreads();
        s[t] += add;
        __syncthreads();
    }
    g_boff[t] = s[t] - v;
}

__global__ void scan3_k(int n, int E) {
    int i = blockIdx.x * blockDim.x + threadIdx.x;
    if (i < n) g_rs[i] += g_boff[i >> 8];
    if (i == 0) g_rs[n] = E;
}

__global__ void fill_k(const int* __restrict__ src, const int* __restrict__ dst, int E) {
    int e = blockIdx.x * blockDim.x + threadIdx.x;
    if (e >= E) return;
    int d = dst[e], s = src[e];
    int slot = g_rs[d] + atomicAdd(&g_fill[d], 1);
    float nm = g_dinv[s] * g_dinv[d];
    g_cpak[slot] = make_int2(s, __float_as_int(nm));
}

// ---------------------------------------------------------------------------
// Split-TF32 tensor GEMM: O[n,NC] = X[n,128] @ W[128,NC].
// 512 threads = 16 warps, 4(M) x 4(N): each warp 16 rows x NC/4 cols.
// A staged once as packed {hi,lo} tf32 (uint2); B double-buffered smem with
// register prefetch; one barrier per chunk; no ALU in the mma chain.
template <int NC, bool XG, bool OG>
__global__ void __launch_bounds__(512)
gemm_tc_k(const float* __restrict__ Xext, float* __restrict__ Oext,
          int wpoff, int n) {
    constexpr int K    = 128;
    constexpr int NCW  = NC / 4;      // cols per warp
    constexpr int NT2  = NCW / 8;     // n-tiles per warp: 4 (NC=128) / 2 (NC=64)
    constexpr int AS2  = K + 4;       // uint2 stride: conflict-free frag reads
    constexpr int BSTR = NC + 2;      // uint4 stride
    constexpr int CE   = 4 * NC;      // chunk elems (uint4): 512 or 256
    __shared__ uint2 As2[64][AS2];    // packed {hi, lo}
    __shared__ uint4 Bs[2][4 * BSTR];

    const float* X = XG ? g_agg : Xext;
    float*       O = OG ? (NC == 128 ? g_h1 : g_h2) : Oext;

    const int tid  = threadIdx.x;
    const int wid  = tid >> 5;
    const int lane = tid & 31;
    const int wm   = wid & 3;         // M warp (16 rows)
    const int wn   = wid >> 2;        // N warp (NC/4 cols)
    const int gq   = lane >> 2;       // 0..7
    const int r    = lane & 3;        // 0..3
    const int row0 = blockIdx.x * 64;

    const uint4* __restrict__ BP = g_wp + wpoff;
    const bool ldr = (tid < CE);      // loader thread for B chunks
    const int  bi  = ldr ? (tid / NC) * BSTR + (tid % NC) : 0;

    // prefetch chunk 0 while staging A
    uint4 pref = make_uint4(0, 0, 0, 0);
    if (ldr) pref = __ldg(&BP[tid]);

    // stage A tile: 64 rows x 128 cols, converted to packed {hi,lo} tf32
    for (int idx = tid; idx < 64 * 32; idx += 512) {
        int rr = idx >> 5, j = idx & 31;
        int grow = row0 + rr;
        float4 v = make_float4(0.f, 0.f, 0.f, 0.f);
        if (grow < n) v = reinterpret_cast<const float4*>(X)[grow * (K / 4) + j];
        As2[rr][j * 4 + 0] = pack_hilo(v.x);
        As2[rr][j * 4 + 1] = pack_hilo(v.y);
        As2[rr][j * 4 + 2] = pack_hilo(v.z);
        As2[rr][j * 4 + 3] = pack_hilo(v.w);
    }

    float acc[NT2][4];
#pragma unroll
    for (int nt = 0; nt < NT2; nt++)
#pragma unroll
        for (int c = 0; c < 4; c++) acc[nt][c] = 0.f;

    // store chunk 0 into buffer 0
    if (ldr) Bs[0][bi] = pref;
    __syncthreads();

    for (int t = 0; t < 16; t++) {
        const int cur = t & 1;
        // issue next chunk's loads; latency overlapped by compute below
        if (t + 1 < 16 && ldr) pref = __ldg(&BP[(t + 1) * CE + tid]);

        int c0 = 8 * t + r, c1 = c0 + 4;
        uint2 p0 = As2[wm * 16 + gq][c0];
        uint2 p1 = As2[wm * 16 + gq + 8][c0];
        uint2 p2 = As2[wm * 16 + gq][c1];
        uint2 p3 = As2[wm * 16 + gq + 8][c1];
        unsigned ah[4] = {p0.x, p1.x, p2.x, p3.x};
        unsigned al[4] = {p0.y, p1.y, p2.y, p3.y};
#pragma unroll
        for (int nt = 0; nt < NT2; nt++) {
            uint4 bp = Bs[cur][r * BSTR + wn * NCW + nt * 8 + gq];
            mma_tf32(acc[nt], ah, bp.x, bp.y);
            mma_tf32(acc[nt], al, bp.x, bp.y);
            mma_tf32(acc[nt], ah, bp.z, bp.w);
        }

        // store next chunk into the other buffer; safe: reaching here means
        // the end-of-(t-1) barrier passed, so nobody still reads buffer cur^1.
        if (t + 1 < 16) {
            if (ldr) Bs[cur ^ 1][bi] = pref;
            __syncthreads();
        }
    }

    const int rA = row0 + wm * 16 + gq;
    const int rB = rA + 8;
#pragma unroll
    for (int nt = 0; nt < NT2; nt++) {
        int col = wn * NCW + nt * 8 + 2 * r;
        if (rA < n)
            *reinterpret_cast<float2*>(&O[rA * NC + col]) = make_float2(acc[nt][0], acc[nt][1]);
        if (rB < n)
            *reinterpret_cast<float2*>(&O[rB * NC + col]) = make_float2(acc[nt][2], acc[nt][3]);
    }
}

// ---------------------------------------------------------------------------
// CSR aggregation, fused self-loop + bias (+relu). GROUP=F/4 lanes per node.
template <int F, bool RELU, bool HG, bool OG>
__global__ void __launch_bounds__(256)
agg_k(float* __restrict__ Oext, const float* __restrict__ b, int n) {
    const float* H = HG ? g_h1 : g_h2;
    float*       O = OG ? g_agg : Oext;
    constexpr int GROUP = F / 4;
    int gtid = blockIdx.x * blockDim.x + threadIdx.x;
    int node = gtid / GROUP;
    int lane = gtid % GROUP;
    if (node >= n) return;

    const float4* __restrict__ H4 = reinterpret_cast<const float4*>(H);
    const int2*   __restrict__ CP = g_cpak;
    float d = g_dinv[node];
    float s2 = d * d;
    float4 h0 = H4[(long long)node * GROUP + lane];
    float4 acc = make_float4(h0.x * s2, h0.y * s2, h0.z * s2, h0.w * s2);

    int p  = g_rs[node];
    int p1 = g_rs[node + 1];
    for (; p + 3 < p1; p += 4) {
        int2 e0 = CP[p], e1 = CP[p+1], e2 = CP[p+2], e3 = CP[p+3];
        float4 hA = H4[(long long)e0.x * GROUP + lane];
        float4 hB = H4[(long long)e1.x * GROUP + lane];
        float4 hC = H4[(long long)e2.x * GROUP + lane];
        float4 hD = H4[(long long)e3.x * GROUP + lane];
        float nA = __int_as_float(e0.y), nB = __int_as_float(e1.y);
        float nC = __int_as_float(e2.y), nD = __int_as_float(e3.y);
        acc.x += nA*hA.x + nB*hB.x + nC*hC.x + nD*hD.x;
        acc.y += nA*hA.y + nB*hB.y + nC*hC.y + nD*hD.y;
        acc.z += nA*hA.z + nB*hB.z + nC*hC.z + nD*hD.z;
        acc.w += nA*hA.w + nB*hB.w + nC*hC.w + nD*hD.w;
    }
    for (; p < p1; p++) {
        int2 e = CP[p];
        float nm = __int_as_float(e.y);
        float4 h = H4[(long long)e.x * GROUP + lane];
        acc.x += nm*h.x; acc.y += nm*h.y; acc.z += nm*h.z; acc.w += nm*h.w;
    }

    float4 bb = reinterpret_cast<const float4*>(b)[lane];
    acc.x += bb.x; acc.y += bb.y; acc.z += bb.z; acc.w += bb.w;
    if (RELU) {
        acc.x = fmaxf(acc.x, 0.f); acc.y = fmaxf(acc.y, 0.f);
        acc.z = fmaxf(acc.z, 0.f); acc.w = fmaxf(acc.w, 0.f);
    }
    reinterpret_cast<float4*>(O)[(long long)node * GROUP + lane] = acc;
}

// ---------------------------------------------------------------------------
extern "C" void kernel_launch(void* const* d_in, const int* in_sizes, int n_in,
                              void* d_out, int out_size) {
    const float* x   = (const float*)d_in[0];
    const int*   ei  = (const int*)d_in[1];   // int32 [2, E]
    const float* W1  = (const float*)d_in[2];
    const float* b1  = (const float*)d_in[3];
    const float* W2  = (const float*)d_in[4];
    const float* b2  = (const float*)d_in[5];
    float*       out = (float*)d_out;

    const int n = in_sizes[0] / FIN;
    const int E = in_sizes[1] / 2;
    const int* src = ei;
    const int* dst = ei + E;

    const int T = 256;
    auto cdiv = [](long long a, long long b) { return (int)((a + b - 1) / b); };
    const int nb = cdiv(n, 256);

    // gemm_tc_k<128> kept as 4th launch (ncu profiled slot).
    deg_init_k <<<cdiv(n, T), T>>>(n);                                    // 1
    deg_count_k<<<cdiv(E, T), T>>>(dst, E);                               // 2
    wcvt_k     <<<cdiv(8192 + 4096, T), T>>>(W1, W2);                     // 3
    gemm_tc_k<HID, false, true><<<cdiv(n, 64), 512>>>(x, nullptr, 0, n);  // 4 <- profiled
    scan1_k    <<<nb, 256>>>(n);                                          // 5
    scan2_k    <<<1, 256>>>(nb);                                          // 6
    scan3_k    <<<cdiv(n, T), T>>>(n, E);                                 // 7
    fill_k     <<<cdiv(E, T), T>>>(src, dst, E);                          // 8
    agg_k<HID, true, true, true><<<cdiv((long long)n * (HID / 4), T), T>>>(nullptr, b1, n); // 9
    gemm_tc_k<FOUT, true, true><<<cdiv(n, 64), 512>>>(nullptr, nullptr, 8192, n);           // 10
    agg_k<FOUT, false, false, false><<<cdiv((long long)n * (FOUT / 4), T), T>>>(out, b2, n);// 11
}

// round 15
// speedup vs baseline: 1.5331x; 1.5331x over previous
#include <cuda_runtime.h>

// ---------------------------------------------------------------------------
// GCNEncoder, CSR aggregation + split-TF32 (3xTF32) tensor-core GEMMs.
// W pre-converted once to packed tf32 hi/lo fragments; A staged as plain fp32
// (cvt in-loop -- measured cheaper than doubling smem); B DOUBLE-BUFFERED in
// smem with register prefetch, one barrier per k-chunk.
//   dinv[i] = rsqrt(indeg[i] + 1)
//   layer(X,W,b): H = X@W
//     out[i] = dinv[i]^2*H[i] + sum_{e: dst=i} dinv[src]*dinv[i]*H[src] + b
//   out = layer2( relu(layer1(x)) )
// edge_index int32. Scratch = __device__ globals. Launch-only host code.
// ---------------------------------------------------------------------------

#define MAXN 50048
#define MAXE 800000
#define FIN  128
#define HID  128
#define FOUT 64

__device__ float g_h1 [MAXN * HID];
__device__ float g_agg[MAXN * HID];
__device__ float g_h2 [MAXN * FOUT];
__device__ float g_dinv[MAXN];
__device__ int   g_deg [MAXN];
__device__ int   g_fill[MAXN];
__device__ int   g_rs  [MAXN + 1];
__device__ int   g_bsum[256];
__device__ int   g_boff[256];
__device__ int2  g_cpak[MAXE];          // {src, float_bits(norm)}
// Packed tf32 W fragments: WP[(t*4+r)*NC + n] = {hi(W[8t+r][n]), hi(W[8t+r+4][n]), lo, lo}
__device__ uint4 g_wp[8192 + 4096];     // W1: 16*4*128, W2: 16*4*64

// ---------------------------------------------------------------------------
__device__ __forceinline__ unsigned f2tf32(float f) {
    unsigned r;
    asm("cvt.rna.tf32.f32 %0, %1;" : "=r"(r) : "f"(f));
    return r;
}

__device__ __forceinline__ void mma_tf32(float (&d)[4], const unsigned (&a)[4],
                                         unsigned b0, unsigned b1) {
    asm volatile(
        "mma.sync.aligned.m16n8k8.row.col.f32.tf32.tf32.f32 "
        "{%0,%1,%2,%3}, {%4,%5,%6,%7}, {%8,%9}, {%0,%1,%2,%3};\n"
        : "+f"(d[0]), "+f"(d[1]), "+f"(d[2]), "+f"(d[3])
        : "r"(a[0]), "r"(a[1]), "r"(a[2]), "r"(a[3]), "r"(b0), "r"(b1));
}

// ---------------------------------------------------------------------------
__global__ void deg_init_k(int n) {
    int i = blockIdx.x * blockDim.x + threadIdx.x;
    if (i < n) { g_deg[i] = 0; g_fill[i] = 0; }
}

__global__ void deg_count_k(const int* __restrict__ dst, int E) {
    int i = blockIdx.x * blockDim.x + threadIdx.x;
    if (i < E) atomicAdd(&g_deg[dst[i]], 1);
}

// Pre-convert W1/W2 into packed tf32 hi/lo fragments.
__global__ void wcvt_k(const float* __restrict__ W1, const float* __restrict__ W2) {
    int i = blockIdx.x * blockDim.x + threadIdx.x;
    float w0, w1;
    if (i < 8192) {                       // W1: t(16) x r(4) x n(128)
        int t = i >> 9, rem = i & 511, r = rem >> 7, nn = rem & 127;
        w0 = W1[(8 * t + r) * 128 + nn];
        w1 = W1[(8 * t + r + 4) * 128 + nn];
    } else if (i < 8192 + 4096) {         // W2: t(16) x r(4) x n(64)
        int j = i - 8192;
        int t = j >> 8, rem = j & 255, r = rem >> 6, nn = rem & 63;
        w0 = W2[(8 * t + r) * 64 + nn];
        w1 = W2[(8 * t + r + 4) * 64 + nn];
    } else return;
    unsigned h0 = f2tf32(w0), h1 = f2tf32(w1);
    unsigned l0 = f2tf32(w0 - __uint_as_float(h0));
    unsigned l1 = f2tf32(w1 - __uint_as_float(h1));
    g_wp[i] = make_uint4(h0, h1, l0, l1);
}

// exclusive scan of g_deg -> g_rs, fused dinv
__global__ void scan1_k(int n) {
    __shared__ int s[256];
    int b = blockIdx.x, t = threadIdx.x;
    int i = b * 256 + t;
    int v = (i < n) ? g_deg[i] : 0;
    if (i < n) g_dinv[i] = rsqrtf((float)(v + 1));
    s[t] = v;
    __syncthreads();
#pragma unroll
    for (int off = 1; off < 256; off <<= 1) {
        int add = (t >= off) ? s[t - off] : 0;
        __syncthreads();
        s[t] += add;
        __syncthreads();
    }
    if (i <= n) g_rs[i] = s[t] - v;
    if (t == 255) g_bsum[b] = s[255];
}

__global__ void scan2_k(int nb) {
    __shared__ int s[256];
    int t = threadIdx.x;
    int v = (t < nb) ? g_bsum[t] : 0;
    s[t] = v;
    __syncthreads();
#pragma unroll
    for (int off = 1; off < 256; off <<= 1) {
        int add = (t >= off) ? s[t - off] : 0;
        __syncthreads();
        s[t] += add;
        __syncthreads();
    }
    g_boff[t] = s[t] - v;
}

__global__ void scan3_k(int n, int E) {
    int i = blockIdx.x * blockDim.x + threadIdx.x;
    if (i < n) g_rs[i] += g_boff[i >> 8];
    if (i == 0) g_rs[n] = E;
}

__global__ void fill_k(const int* __restrict__ src, const int* __restrict__ dst, int E) {
    int e = blockIdx.x * blockDim.x + threadIdx.x;
    if (e >= E) return;
    int d = dst[e], s = src[e];
    int slot = g_rs[d] + atomicAdd(&g_fill[d], 1);
    float nm = g_dinv[s] * g_dinv[d];
    g_cpak[slot] = make_int2(s, __float_as_int(nm));
}

// ---------------------------------------------------------------------------
// Split-TF32 tensor GEMM: O[n,NC] = X[n,128] @ W[128,NC].
// 512 threads = 16 warps, 4(M) x 4(N): each warp 16 rows x NC/4 cols.
// A staged once as plain fp32 (cvt in mainloop); B double-buffered smem with
// register prefetch; one barrier per k-chunk.
template <int NC, bool XG, bool OG>
__global__ void __launch_bounds__(512)
gemm_tc_k(const float* __restrict__ Xext, float* __restrict__ Oext,
          int wpoff, int n) {
    constexpr int K    = 128;
    constexpr int NCW  = NC / 4;      // cols per warp
    constexpr int NT2  = NCW / 8;     // n-tiles per warp: 4 (NC=128) / 2 (NC=64)
    constexpr int AS   = K + 4;       // float stride: 4gq+r distinct mod 32
    constexpr int BSTR = NC + 2;      // uint4 stride
    constexpr int CE   = 4 * NC;      // chunk elems (uint4): 512 or 256
    __shared__ float As[64][AS];
    __shared__ uint4 Bs[2][4 * BSTR];

    const float* X = XG ? g_agg : Xext;
    float*       O = OG ? (NC == 128 ? g_h1 : g_h2) : Oext;

    const int tid  = threadIdx.x;
    const int wid  = tid >> 5;
    const int lane = tid & 31;
    const int wm   = wid & 3;         // M warp (16 rows)
    const int wn   = wid >> 2;        // N warp (NC/4 cols)
    const int gq   = lane >> 2;       // 0..7
    const int r    = lane & 3;        // 0..3
    const int row0 = blockIdx.x * 64;

    const uint4* __restrict__ BP = g_wp + wpoff;
    const bool ldr = (tid < CE);      // loader thread for B chunks
    const int  bi  = ldr ? (tid / NC) * BSTR + (tid % NC) : 0;

    // prefetch chunk 0 while staging A
    uint4 pref = make_uint4(0, 0, 0, 0);
    if (ldr) pref = __ldg(&BP[tid]);

    // stage A tile: 64 rows x 128 cols
    for (int idx = tid; idx < 64 * 32; idx += 512) {
        int rr = idx >> 5, j = idx & 31;
        int grow = row0 + rr;
        float4 v = make_float4(0.f, 0.f, 0.f, 0.f);
        if (grow < n) v = reinterpret_cast<const float4*>(X)[grow * (K / 4) + j];
        *reinterpret_cast<float4*>(&As[rr][j * 4]) = v;
    }

    float acc[NT2][4];
#pragma unroll
    for (int nt = 0; nt < NT2; nt++)
#pragma unroll
        for (int c = 0; c < 4; c++) acc[nt][c] = 0.f;

    // store chunk 0 into buffer 0
    if (ldr) Bs[0][bi] = pref;
    __syncthreads();

    for (int t = 0; t < 16; t++) {
        const int cur = t & 1;
        // issue next chunk's loads; latency overlapped by compute below
        if (t + 1 < 16 && ldr) pref = __ldg(&BP[(t + 1) * CE + tid]);

        int c0 = 8 * t + r, c1 = c0 + 4;
        float a0 = As[wm * 16 + gq][c0];
        float a1 = As[wm * 16 + gq + 8][c0];
        float a2 = As[wm * 16 + gq][c1];
        float a3 = As[wm * 16 + gq + 8][c1];
        unsigned ah[4] = {f2tf32(a0), f2tf32(a1), f2tf32(a2), f2tf32(a3)};
        unsigned al[4] = {
            f2tf32(a0 - __uint_as_float(ah[0])),
            f2tf32(a1 - __uint_as_float(ah[1])),
            f2tf32(a2 - __uint_as_float(ah[2])),
            f2tf32(a3 - __uint_as_float(ah[3]))};
#pragma unroll
        for (int nt = 0; nt < NT2; nt++) {
            uint4 bp = Bs[cur][r * BSTR + wn * NCW + nt * 8 + gq];
            mma_tf32(acc[nt], ah, bp.x, bp.y);
            mma_tf32(acc[nt], al, bp.x, bp.y);
            mma_tf32(acc[nt], ah, bp.z, bp.w);
        }

        // store next chunk into the other buffer; safe: reaching here means
        // the end-of-(t-1) barrier passed, so nobody still reads buffer cur^1.
        if (t + 1 < 16) {
            if (ldr) Bs[cur ^ 1][bi] = pref;
            __syncthreads();
        }
    }

    const int rA = row0 + wm * 16 + gq;
    const int rB = rA + 8;
#pragma unroll
    for (int nt = 0; nt < NT2; nt++) {
        int col = wn * NCW + nt * 8 + 2 * r;
        if (rA < n)
            *reinterpret_cast<float2*>(&O[rA * NC + col]) = make_float2(acc[nt][0], acc[nt][1]);
        if (rB < n)
            *reinterpret_cast<float2*>(&O[rB * NC + col]) = make_float2(acc[nt][2], acc[nt][3]);
    }
}

// ---------------------------------------------------------------------------
// CSR aggregation, fused self-loop + bias (+relu). GROUP=F/4 lanes per node.
template <int F, bool RELU, bool HG, bool OG>
__global__ void __launch_bounds__(256)
agg_k(float* __restrict__ Oext, const float* __restrict__ b, int n) {
    const float* H = HG ? g_h1 : g_h2;
    float*       O = OG ? g_agg : Oext;
    constexpr int GROUP = F / 4;
    int gtid = blockIdx.x * blockDim.x + threadIdx.x;
    int node = gtid / GROUP;
    int lane = gtid % GROUP;
    if (node >= n) return;

    const float4* __restrict__ H4 = reinterpret_cast<const float4*>(H);
    const int2*   __restrict__ CP = g_cpak;
    float d = g_dinv[node];
    float s2 = d * d;
    float4 h0 = H4[(long long)node * GROUP + lane];
    float4 acc = make_float4(h0.x * s2, h0.y * s2, h0.z * s2, h0.w * s2);

    int p  = g_rs[node];
    int p1 = g_rs[node + 1];
    for (; p + 3 < p1; p += 4) {
        int2 e0 = CP[p], e1 = CP[p+1], e2 = CP[p+2], e3 = CP[p+3];
        float4 hA = H4[(long long)e0.x * GROUP + lane];
        float4 hB = H4[(long long)e1.x * GROUP + lane];
        float4 hC = H4[(long long)e2.x * GROUP + lane];
        float4 hD = H4[(long long)e3.x * GROUP + lane];
        float nA = __int_as_float(e0.y), nB = __int_as_float(e1.y);
        float nC = __int_as_float(e2.y), nD = __int_as_float(e3.y);
        acc.x += nA*hA.x + nB*hB.x + nC*hC.x + nD*hD.x;
        acc.y += nA*hA.y + nB*hB.y + nC*hC.y + nD*hD.y;
        acc.z += nA*hA.z + nB*hB.z + nC*hC.z + nD*hD.z;
        acc.w += nA*hA.w + nB*hB.w + nC*hC.w + nD*hD.w;
    }
    for (; p < p1; p++) {
        int2 e = CP[p];
        float nm = __int_as_float(e.y);
        float4 h = H4[(long long)e.x * GROUP + lane];
        acc.x += nm*h.x; acc.y += nm*h.y; acc.z += nm*h.z; acc.w += nm*h.w;
    }

    float4 bb = reinterpret_cast<const float4*>(b)[lane];
    acc.x += bb.x; acc.y += bb.y; acc.z += bb.z; acc.w += bb.w;
    if (RELU) {
        acc.x = fmaxf(acc.x, 0.f); acc.y = fmaxf(acc.y, 0.f);
        acc.z = fmaxf(acc.z, 0.f); acc.w = fmaxf(acc.w, 0.f);
    }
    reinterpret_cast<float4*>(O)[(long long)node * GROUP + lane] = acc;
}

// ---------------------------------------------------------------------------
extern "C" void kernel_launch(void* const* d_in, const int* in_sizes, int n_in,
                              void* d_out, int out_size) {
    const float* x   = (const float*)d_in[0];
    const int*   ei  = (const int*)d_in[1];   // int32 [2, E]
    const float* W1  = (const float*)d_in[2];
    const float* b1  = (const float*)d_in[3];
    const float* W2  = (const float*)d_in[4];
    const float* b2  = (const float*)d_in[5];
    float*       out = (float*)d_out;

    const int n = in_sizes[0] / FIN;
    const int E = in_sizes[1] / 2;
    const int* src = ei;
    const int* dst = ei + E;

    const int T = 256;
    auto cdiv = [](long long a, long long b) { return (int)((a + b - 1) / b); };
    const int nb = cdiv(n, 256);

    // gemm_tc_k<128> kept as 4th launch (ncu profiled slot).
    deg_init_k <<<cdiv(n, T), T>>>(n);                                    // 1
    deg_count_k<<<cdiv(E, T), T>>>(dst, E);                               // 2
    wcvt_k     <<<cdiv(8192 + 4096, T), T>>>(W1, W2);                     // 3
    gemm_tc_k<HID, false, true><<<cdiv(n, 64), 512>>>(x, nullptr, 0, n);  // 4 <- profiled
    scan1_k    <<<nb, 256>>>(n);                                          // 5
    scan2_k    <<<1, 256>>>(nb);                                          // 6
    scan3_k    <<<cdiv(n, T), T>>>(n, E);                                 // 7
    fill_k     <<<cdiv(E, T), T>>>(src, dst, E);                          // 8
    agg_k<HID, true, true, true><<<cdiv((long long)n * (HID / 4), T), T>>>(nullptr, b1, n); // 9
    gemm_tc_k<FOUT, true, true><<<cdiv(n, 64), 512>>>(nullptr, nullptr, 8192, n);           // 10
    agg_k<FOUT, false, false, false><<<cdiv((long long)n * (FOUT / 4), T), T>>>(out, b2, n);// 11
}